// round 1
// baseline (speedup 1.0000x reference)
#include <cuda_runtime.h>
#include <stdint.h>

#define NBOX   100800
#define NC     80
#define ROW    85
#define TOPK   4096
#define CAP    8192
#define BINS   4096
#define MAXDET 1000
#define CONF_T 0.4f
#define IOU_T  0.45f
#define MAXWH  7680.0f
#define BITS04 0x3ECCCCCDu   // bits of 0.4f

// ---------------- scratch (device globals; no allocation allowed) ----------
__device__ float              g_score[NBOX];
__device__ unsigned char      g_cls[NBOX];
__device__ int                g_hist[BINS];
__device__ int                g_tbin;
__device__ unsigned long long g_cand[CAP];
__device__ int                g_ccnt;
__device__ float              g_sscore[TOPK];
__device__ int                g_scls[TOPK];
__device__ float              g_ox1[TOPK], g_oy1[TOPK], g_ox2[TOPK], g_oy2[TOPK], g_oarea[TOPK];
__device__ float              g_bb[TOPK][4];
__device__ unsigned char      g_keep[TOPK];

// ---------------- K0: per-replay reset ------------------------------------
__global__ void k0_init() {
    int i = blockIdx.x * blockDim.x + threadIdx.x;
    if (i < BINS) g_hist[i] = 0;
    if (i < CAP)  g_cand[i] = 0xFFFFFFFFFFFFFFFFULL;
    if (i == 0)   g_ccnt = 0;
}

// ---------------- K1: score + class argmax + histogram ---------------------
__global__ void __launch_bounds__(256) k1_score(const float* __restrict__ pred) {
    __shared__ int sh[BINS];
    for (int i = threadIdx.x; i < BINS; i += 256) sh[i] = 0;
    __syncthreads();

    int i = blockIdx.x * 256 + threadIdx.x;
    if (i < NBOX) {
        const float* p = pred + (size_t)i * ROW;
        float obj = p[4];
        float best = -1.0f; int bc = 0;
        #pragma unroll
        for (int c = 0; c < NC; c++) {
            float v = __fmul_rn(p[5 + c], obj);   // cls_conf = cls * obj (exact ref op)
            if (v > best) { best = v; bc = c; }   // strict > : first index wins ties (argmax)
        }
        g_score[i] = best;
        g_cls[i]   = (unsigned char)bc;
        if (best > CONF_T) {
            unsigned b = (__float_as_uint(best) - BITS04) >> 12;  // monotone in score
            if (b >= BINS) b = BINS - 1;
            atomicAdd(&sh[b], 1);
        }
    }
    __syncthreads();
    for (int j = threadIdx.x; j < BINS; j += 256)
        if (sh[j]) atomicAdd(&g_hist[j], sh[j]);
}

// ---------------- K2: find threshold bin (cum from top >= TOPK) ------------
__global__ void k2_thresh() {
    __shared__ int chunk[128];
    int t = threadIdx.x;
    int s = 0;
    for (int b = t * 32; b < t * 32 + 32; b++) s += g_hist[b];
    chunk[t] = s;
    __syncthreads();
    if (t == 0) {
        int cum = 0, T = 0;
        for (int c = 127; c >= 0; c--) {
            if (cum + chunk[c] >= TOPK) {
                for (int b = c * 32 + 31; b >= c * 32; b--) {
                    cum += g_hist[b];
                    if (cum >= TOPK) { T = b; break; }
                }
                break;
            }
            cum += chunk[c];
        }
        g_tbin = T;   // stays 0 if fewer than TOPK valid boxes
    }
}

// ---------------- K3: gather candidate keys --------------------------------
__global__ void __launch_bounds__(256) k3_gather() {
    int i = blockIdx.x * 256 + threadIdx.x;
    if (i >= NBOX) return;
    float s = g_score[i];
    if (s > CONF_T) {
        unsigned b = (__float_as_uint(s) - BITS04) >> 12;
        if (b >= BINS) b = BINS - 1;
        if ((int)b >= g_tbin) {
            int p = atomicAdd(&g_ccnt, 1);
            if (p < CAP) {
                // key: (~score_bits)<<32 | idx  -> ascending sort == score desc, idx asc
                unsigned long long key =
                    ((unsigned long long)(~__float_as_uint(s)) << 32) | (unsigned)i;
                g_cand[p] = key;
            }
        }
    }
}

// ---------------- K4: one-block bitonic sort + derive per-slot data --------
__global__ void __launch_bounds__(1024) k4_sort(const float* __restrict__ pred) {
    extern __shared__ unsigned long long sk[];
    int t = threadIdx.x;
    for (int i = t; i < CAP; i += 1024) sk[i] = g_cand[i];
    __syncthreads();

    for (int k = 2; k <= CAP; k <<= 1) {
        for (int j = k >> 1; j > 0; j >>= 1) {
            for (int i = t; i < CAP; i += 1024) {
                int l = i ^ j;
                if (l > i) {
                    unsigned long long a = sk[i], b = sk[l];
                    bool up = ((i & k) == 0);
                    if ((a > b) == up) { sk[i] = b; sk[l] = a; }
                }
            }
            __syncthreads();
        }
    }

    for (int jj = t; jj < TOPK; jj += 1024) {
        unsigned long long key = sk[jj];
        g_keep[jj] = 0;
        if (key == 0xFFFFFFFFFFFFFFFFULL) {
            g_sscore[jj] = -1.0f;
            g_scls[jj]   = 255;           // never matches a class block
        } else {
            unsigned idx = (unsigned)(key & 0xFFFFFFFFu);
            float s = __uint_as_float(~(unsigned)(key >> 32));
            int c = g_cls[idx];
            const float* p = pred + (size_t)idx * ROW;
            float x = p[0], y = p[1], w = p[2], h = p[3];
            float hw = __fmul_rn(w, 0.5f), hh = __fmul_rn(h, 0.5f);
            float b0 = __fsub_rn(x, hw), b1 = __fsub_rn(y, hh);
            float b2 = __fadd_rn(x, hw), b3 = __fadd_rn(y, hh);
            float off = __fmul_rn((float)c, MAXWH);
            float o0 = __fadd_rn(b0, off), o1 = __fadd_rn(b1, off);
            float o2 = __fadd_rn(b2, off), o3 = __fadd_rn(b3, off);
            g_sscore[jj] = s;
            g_scls[jj]   = c;
            g_bb[jj][0] = b0; g_bb[jj][1] = b1; g_bb[jj][2] = b2; g_bb[jj][3] = b3;
            g_ox1[jj] = o0; g_oy1[jj] = o1; g_ox2[jj] = o2; g_oy2[jj] = o3;
            g_oarea[jj] = __fmul_rn(__fsub_rn(o2, o0), __fsub_rn(o3, o1));
        }
    }
}

// ---------------- K5: per-class greedy NMS (class offsets are disjoint) ----
__global__ void __launch_bounds__(32) k5_nms() {
    __shared__ int list[TOPK];
    __shared__ int keptl[TOPK];
    const unsigned full = 0xffffffffu;
    int lane = threadIdx.x;
    int myc  = blockIdx.x;

    // stable compaction: positions of this class, sorted order preserved
    int cnt = 0;
    for (int base = 0; base < TOPK; base += 32) {
        int c = g_scls[base + lane];
        unsigned m = __ballot_sync(full, c == myc);
        if (c == myc) list[cnt + __popc(m & ((1u << lane) - 1u))] = base + lane;
        cnt += __popc(m);
    }
    __syncwarp();

    int nk = 0;
    for (int tt = 0; tt < cnt; tt++) {
        int pos = list[tt];
        float x1 = g_ox1[pos], y1 = g_oy1[pos];
        float x2 = g_ox2[pos], y2 = g_oy2[pos];
        float a  = g_oarea[pos];
        bool sup = false;
        for (int b0 = 0; b0 < nk && !sup; b0 += 32) {
            bool s = false;
            int ii = b0 + lane;
            if (ii < nk) {
                int kp = keptl[ii];
                float ltx = fmaxf(g_ox1[kp], x1);
                float lty = fmaxf(g_oy1[kp], y1);
                float rbx = fminf(g_ox2[kp], x2);
                float rby = fminf(g_oy2[kp], y2);
                float ww  = fmaxf(__fsub_rn(rbx, ltx), 0.0f);
                float hh  = fmaxf(__fsub_rn(rby, lty), 0.0f);
                float inter = __fmul_rn(ww, hh);
                float den = __fadd_rn(__fsub_rn(__fadd_rn(g_oarea[kp], a), inter), 1e-9f);
                float iou = __fdiv_rn(inter, den);
                s = iou > IOU_T;
            }
            sup = __any_sync(full, s);
        }
        if (!sup) {
            if (lane == 0) { keptl[nk] = pos; g_keep[pos] = 1; }
            nk++;
        }
        __syncwarp();
    }
}

// ---------------- K6: zero output, write first MAXDET kept rows ------------
__global__ void __launch_bounds__(256) k6_out(float* __restrict__ out) {
    for (int i = threadIdx.x; i < MAXDET * 6; i += 256) out[i] = 0.0f;
    __syncthreads();
    if (threadIdx.x < 32) {
        int lane = threadIdx.x;
        int total = 0;
        for (int base = 0; base < TOPK && total < MAXDET; base += 32) {
            int k = g_keep[base + lane];
            unsigned m = __ballot_sync(0xffffffffu, k != 0);
            int r = total + __popc(m & ((1u << lane) - 1u));
            if (k && r < MAXDET) {
                int pos = base + lane;
                out[r * 6 + 0] = g_bb[pos][0];
                out[r * 6 + 1] = g_bb[pos][1];
                out[r * 6 + 2] = g_bb[pos][2];
                out[r * 6 + 3] = g_bb[pos][3];
                out[r * 6 + 4] = g_sscore[pos];
                out[r * 6 + 5] = (float)g_scls[pos];
            }
            total += __popc(m);
        }
    }
}

// ---------------- launch ----------------------------------------------------
extern "C" void kernel_launch(void* const* d_in, const int* in_sizes, int n_in,
                              void* d_out, int out_size) {
    (void)in_sizes; (void)n_in; (void)out_size;
    const float* pred = (const float*)d_in[0];
    float* out = (float*)d_out;

    cudaFuncSetAttribute(k4_sort, cudaFuncAttributeMaxDynamicSharedMemorySize,
                         CAP * (int)sizeof(unsigned long long));

    k0_init<<<(CAP + 255) / 256, 256>>>();
    k1_score<<<(NBOX + 255) / 256, 256>>>(pred);
    k2_thresh<<<1, 128>>>();
    k3_gather<<<(NBOX + 255) / 256, 256>>>();
    k4_sort<<<1, 1024, CAP * (int)sizeof(unsigned long long)>>>(pred);
    k5_nms<<<NC, 32>>>();
    k6_out<<<1, 256>>>(out);
}

// round 2
// speedup vs baseline: 2.1964x; 2.1964x over previous
#include <cuda_runtime.h>
#include <stdint.h>

#define NBOX   100800
#define NC     80
#define ROW    85
#define TOPK   4096
#define BINS   4096
#define CAPC   512
#define BCAP   1024
#define FCAP   2048
#define MAXDET 1000
#define CONF_T 0.4f
#define IOU_T  0.45f
#define MAXWH  7680.0f
#define BITS04 0x3ECCCCCDu
#define PADKEY 0xFFFFFFFFFFFFFFFFULL

__device__ float              g_score[NBOX];
__device__ unsigned char      g_cls[NBOX];
__device__ int                g_hist[BINS];
__device__ int                g_hist2[BINS];
__device__ int                g_tbin, g_need;
__device__ int                g_ccount[NC];
__device__ unsigned long long g_ckey[NC * CAPC];
__device__ unsigned long long g_btbl[BCAP];
__device__ int                g_bcnt;
__device__ unsigned long long g_fkey[TOPK + 256];
__device__ int                g_fcnt;

__global__ void k0_init(float* __restrict__ out) {
    int i = blockIdx.x * blockDim.x + threadIdx.x;
    if (i < BINS) { g_hist[i] = 0; g_hist2[i] = 0; }
    if (i < NC)   g_ccount[i] = 0;
    if (i == 0)   { g_bcnt = 0; g_fcnt = 0; }
    if (i < MAXDET * 6) out[i] = 0.0f;
}

__global__ void __launch_bounds__(256) k1_score(const float* __restrict__ pred) {
    __shared__ int sh[BINS];
    for (int i = threadIdx.x; i < BINS; i += 256) sh[i] = 0;
    __syncthreads();

    int i = blockIdx.x * 256 + threadIdx.x;
    if (i < NBOX) {
        const float* p = pred + (size_t)i * ROW;
        float obj = p[4];
        float best = -1.0f; int bc = 0;
        #pragma unroll
        for (int c = 0; c < NC; c++) {
            float v = __fmul_rn(p[5 + c], obj);
            if (v > best) { best = v; bc = c; }
        }
        g_score[i] = best;
        g_cls[i]   = (unsigned char)bc;
        if (best > CONF_T) {
            unsigned b = (__float_as_uint(best) - BITS04) >> 12;
            if (b >= BINS) b = BINS - 1;
            atomicAdd(&sh[b], 1);
        }
    }
    __syncthreads();
    for (int j = threadIdx.x; j < BINS; j += 256)
        if (sh[j]) atomicAdd(&g_hist[j], sh[j]);
}

__global__ void k2_thresh() {
    __shared__ int chunk[128];
    int t = threadIdx.x;
    int s = 0;
    for (int b = t * 32; b < t * 32 + 32; b++) s += g_hist[b];
    chunk[t] = s;
    __syncthreads();
    if (t == 0) {
        int cum = 0, tb = 0, A = 0; bool found = false;
        for (int c = 127; c >= 0 && !found; c--) {
            if (cum + chunk[c] >= TOPK) {
                for (int b = c * 32 + 31; b >= c * 32; b--) {
                    if (cum + g_hist[b] >= TOPK) { tb = b; A = cum; found = true; break; }
                    cum += g_hist[b];
                }
            } else cum += chunk[c];
        }
        if (!found) { tb = 0; A = cum - g_hist[0]; }
        g_tbin = tb;
        g_need = TOPK - A;
    }
}

__global__ void __launch_bounds__(256) k3_gather() {
    int i = blockIdx.x * 256 + threadIdx.x;
    if (i >= NBOX) return;
    float s = g_score[i];
    if (s > CONF_T) {
        unsigned sb = __float_as_uint(s);
        unsigned b  = (sb - BITS04) >> 12;
        if (b >= BINS) b = BINS - 1;
        int tb = g_tbin;
        if ((int)b >= tb) {
            unsigned long long key = ((unsigned long long)(~sb) << 32) | (unsigned)i;
            if ((int)b > tb) {
                int c = g_cls[i];
                int p = atomicAdd(&g_ccount[c], 1);
                if (p < CAPC) g_ckey[c * CAPC + p] = key;
            } else {
                int p = atomicAdd(&g_bcnt, 1);
                if (p < BCAP) g_btbl[p] = key;
            }
        }
    }
}

__global__ void __launch_bounds__(256) k5_nms(const float* __restrict__ pred) {
    __shared__ unsigned long long skey[CAPC];
    __shared__ unsigned long long sbt[BCAP];
    __shared__ float sx1[CAPC], sy1[CAPC], sx2[CAPC], sy2[CAPC], sar[CAPC];
    __shared__ unsigned char skeep[CAPC];
    __shared__ int s_extra;

    const unsigned full = 0xffffffffu;
    int t = threadIdx.x, lane = t & 31;
    int myc = blockIdx.x;
    int cnt = min(g_ccount[myc], CAPC);
    int m = min(g_bcnt, BCAP);
    int need = g_need;

    if (t == 0) s_extra = 0;
    for (int i = t; i < m; i += 256) sbt[i] = g_btbl[i];
    __syncthreads();

    for (int e = t; e < m; e += 256) {
        unsigned long long k = sbt[e];
        int r = 0;
        for (int j = 0; j < m; j++) r += (sbt[j] < k);
        if (r < need) {
            unsigned idx = (unsigned)k;
            if (g_cls[idx] == (unsigned char)myc) {
                int p = atomicAdd(&s_extra, 1);
                if (cnt + p < CAPC) skey[cnt + p] = k;
            }
        }
    }
    for (int i = t; i < cnt; i += 256) skey[i] = g_ckey[myc * CAPC + i];
    __syncthreads();

    int tot = cnt + s_extra;
    if (tot > CAPC) tot = CAPC;
    for (int i = t; i < CAPC; i += 256) if (i >= tot) skey[i] = PADKEY;
    __syncthreads();

    for (int k = 2; k <= CAPC; k <<= 1)
        for (int j = k >> 1; j > 0; j >>= 1) {
            for (int i = t; i < CAPC; i += 256) {
                int l = i ^ j;
                if (l > i) {
                    unsigned long long a = skey[i], b = skey[l];
                    bool up = ((i & k) == 0);
                    if ((a > b) == up) { skey[i] = b; skey[l] = a; }
                }
            }
            __syncthreads();
        }

    float off = __fmul_rn((float)myc, MAXWH);
    for (int i = t; i < tot; i += 256) {
        unsigned idx = (unsigned)skey[i];
        const float* p = pred + (size_t)idx * ROW;
        float x = p[0], y = p[1], w = p[2], h = p[3];
        float hw = __fmul_rn(w, 0.5f), hh = __fmul_rn(h, 0.5f);
        float b0 = __fsub_rn(x, hw), b1 = __fsub_rn(y, hh);
        float b2 = __fadd_rn(x, hw), b3 = __fadd_rn(y, hh);
        float q0 = __fadd_rn(b0, off), q1 = __fadd_rn(b1, off);
        float q2 = __fadd_rn(b2, off), q3 = __fadd_rn(b3, off);
        sx1[i] = q0; sy1[i] = q1; sx2[i] = q2; sy2[i] = q3;
        sar[i] = __fmul_rn(__fsub_rn(q2, q0), __fsub_rn(q3, q1));
        skeep[i] = 1;
    }
    __syncthreads();

    if (t < 32) {
        for (int tt = 0; tt < tot; tt++) {
            if (skeep[tt]) {
                float x1 = sx1[tt], y1 = sy1[tt], x2 = sx2[tt], y2 = sy2[tt], a = sar[tt];
                for (int j = tt + 1 + lane; j < tot; j += 32) {
                    float ltx = fmaxf(sx1[j], x1);
                    float lty = fmaxf(sy1[j], y1);
                    float rbx = fminf(sx2[j], x2);
                    float rby = fminf(sy2[j], y2);
                    float ww  = fmaxf(__fsub_rn(rbx, ltx), 0.0f);
                    float hh  = fmaxf(__fsub_rn(rby, lty), 0.0f);
                    float inter = __fmul_rn(ww, hh);
                    float den = __fadd_rn(__fsub_rn(__fadd_rn(a, sar[j]), inter), 1e-9f);
                    if (__fdiv_rn(inter, den) > IOU_T) skeep[j] = 0;
                }
            }
            __syncwarp(full);
        }
    }
    __syncthreads();

    for (int i = t; i < CAPC; i += 256) {
        bool kp = (i < tot) && skeep[i];
        unsigned msk = __ballot_sync(full, kp);
        int base = 0;
        if (lane == 0 && msk) base = atomicAdd(&g_fcnt, __popc(msk));
        base = __shfl_sync(full, base, 0);
        if (kp) {
            g_fkey[base + __popc(msk & ((1u << lane) - 1u))] = skey[i];
            unsigned sb = ~(unsigned)(skey[i] >> 32);
            unsigned b = (sb - BITS04) >> 12;
            if (b >= BINS) b = BINS - 1;
            atomicAdd(&g_hist2[b], 1);
        }
    }
}

__global__ void __launch_bounds__(1024) k8_final(const float* __restrict__ pred,
                                                 float* __restrict__ out) {
    __shared__ unsigned long long fk[FCAP];
    __shared__ int chunk[128];
    __shared__ int s_T2, s_cnt;
    int t = threadIdx.x, lane = t & 31;

    if (t < 128) {
        int s = 0;
        for (int b = t * 32; b < t * 32 + 32; b++) s += g_hist2[b];
        chunk[t] = s;
    }
    if (t == 0) s_cnt = 0;
    __syncthreads();
    if (t == 0) {
        int cum = 0, T2 = 0; bool found = false;
        for (int c = 127; c >= 0 && !found; c--) {
            if (cum + chunk[c] >= MAXDET) {
                for (int b = c * 32 + 31; b >= c * 32; b--) {
                    if (cum + g_hist2[b] >= MAXDET) { T2 = b; found = true; break; }
                    cum += g_hist2[b];
                }
            } else cum += chunk[c];
        }
        s_T2 = found ? T2 : 0;
    }
    for (int i = t; i < FCAP; i += 1024) fk[i] = PADKEY;
    __syncthreads();

    int K = min(g_fcnt, TOPK + 256);
    int T2 = s_T2;
    int Kr = (K + 31) & ~31;
    for (int i = t; i < Kr; i += 1024) {
        bool take = false;
        unsigned long long key = PADKEY;
        if (i < K) {
            key = g_fkey[i];
            unsigned sb = ~(unsigned)(key >> 32);
            unsigned b = (sb - BITS04) >> 12;
            if (b >= BINS) b = BINS - 1;
            take = ((int)b >= T2);
        }
        unsigned msk = __ballot_sync(0xffffffffu, take);
        int base = 0;
        if (lane == 0 && msk) base = atomicAdd(&s_cnt, __popc(msk));
        base = __shfl_sync(0xffffffffu, base, 0);
        if (take) {
            int p = base + __popc(msk & ((1u << lane) - 1u));
            if (p < FCAP) fk[p] = key;
        }
    }
    __syncthreads();

    for (int k = 2; k <= FCAP; k <<= 1)
        for (int j = k >> 1; j > 0; j >>= 1) {
            for (int i = t; i < FCAP; i += 1024) {
                int l = i ^ j;
                if (l > i) {
                    unsigned long long a = fk[i], b = fk[l];
                    bool up = ((i & k) == 0);
                    if ((a > b) == up) { fk[i] = b; fk[l] = a; }
                }
            }
            __syncthreads();
        }

    int m2 = min(s_cnt, FCAP);
    for (int r = t; r < MAXDET; r += 1024) {
        if (r < m2) {
            unsigned long long key = fk[r];
            unsigned idx = (unsigned)key;
            float s = __uint_as_float(~(unsigned)(key >> 32));
            const float* p = pred + (size_t)idx * ROW;
            float x = p[0], y = p[1], w = p[2], h = p[3];
            float hw = __fmul_rn(w, 0.5f), hh = __fmul_rn(h, 0.5f);
            out[r * 6 + 0] = __fsub_rn(x, hw);
            out[r * 6 + 1] = __fsub_rn(y, hh);
            out[r * 6 + 2] = __fadd_rn(x, hw);
            out[r * 6 + 3] = __fadd_rn(y, hh);
            out[r * 6 + 4] = s;
            out[r * 6 + 5] = (float)g_cls[idx];
        }
    }
}

extern "C" void kernel_launch(void* const* d_in, const int* in_sizes, int n_in,
                              void* d_out, int out_size) {
    (void)in_sizes; (void)n_in; (void)out_size;
    const float* pred = (const float*)d_in[0];
    float* out = (float*)d_out;

    k0_init<<<40, 256>>>(out);
    k1_score<<<(NBOX + 255) / 256, 256>>>(pred);
    k2_thresh<<<1, 128>>>();
    k3_gather<<<(NBOX + 255) / 256, 256>>>();
    k5_nms<<<NC, 256>>>(pred);
    k8_final<<<1, 1024>>>(pred, out);
}

// round 4
// speedup vs baseline: 2.2996x; 1.0470x over previous
#include <cuda_runtime.h>
#include <stdint.h>

#define NBOX   100800
#define NC     80
#define ROW    85
#define TOPK   4096
#define BINS   4096
#define CAPC   512
#define BCAP   1024
#define FCAP   2048
#define MAXDET 1000
#define RPB    128           // rows per k1 block
#define CONF_T 0.4f
#define IOU_T  0.45f
#define MAXWH  7680.0f
#define BITS04 0x3ECCCCCDu
#define PADKEY 0xFFFFFFFFFFFFFFFFULL

__device__ float              g_score[NBOX];
__device__ unsigned char      g_cls[NBOX];
__device__ int                g_hist[BINS];
__device__ int                g_hist2[BINS];
__device__ int                g_tbin, g_need;
__device__ int                g_ccount[NC];
__device__ unsigned long long g_ckey[NC * CAPC];
__device__ unsigned long long g_btbl[BCAP];
__device__ int                g_bcnt;
__device__ unsigned long long g_fkey[TOPK + 256];
__device__ int                g_fcnt;

__global__ void k0_init(float* __restrict__ out) {
    int i = blockIdx.x * blockDim.x + threadIdx.x;
    if (i < BINS) { g_hist[i] = 0; g_hist2[i] = 0; }
    if (i < NC)   g_ccount[i] = 0;
    if (i == 0)   { g_bcnt = 0; g_fcnt = 0; }
    if (i < MAXDET * 6) out[i] = 0.0f;
}

// K1: stage 128 rows into smem with coalesced float4 loads, then per-thread
// argmax from conflict-free smem (stride 85 is odd -> gcd(85,32)=1).
__global__ void __launch_bounds__(RPB) k1_score(const float* __restrict__ pred) {
    extern __shared__ float srow[];          // RPB * ROW floats (43520 B)
    __shared__ int sh[BINS];                 // 16 KB
    int t = threadIdx.x;
    for (int i = t; i < BINS; i += RPB) sh[i] = 0;

    int b0 = blockIdx.x * RPB;
    int nrows = NBOX - b0; if (nrows > RPB) nrows = RPB;
    int nf4 = (nrows * ROW) >> 2;            // nrows divisible by 4 -> exact
    const float4* src = (const float4*)(pred + (size_t)b0 * ROW);
    float4* dst = (float4*)srow;
    for (int i = t; i < nf4; i += RPB) dst[i] = src[i];
    __syncthreads();

    if (t < nrows) {
        const float* p = srow + t * ROW;
        float obj = p[4];
        float best = -1.0f; int bc = 0;
        #pragma unroll
        for (int c = 0; c < NC; c++) {
            float v = __fmul_rn(p[5 + c], obj);
            if (v > best) { best = v; bc = c; }
        }
        int gi = b0 + t;
        g_score[gi] = best;
        g_cls[gi]   = (unsigned char)bc;
        if (best > CONF_T) {
            unsigned b = (__float_as_uint(best) - BITS04) >> 12;
            if (b >= BINS) b = BINS - 1;
            atomicAdd(&sh[b], 1);
        }
    }
    __syncthreads();
    for (int j = t; j < BINS; j += RPB)
        if (sh[j]) atomicAdd(&g_hist[j], sh[j]);
}

__global__ void k2_thresh() {
    __shared__ int chunk[128];
    int t = threadIdx.x;
    int s = 0;
    for (int b = t * 32; b < t * 32 + 32; b++) s += g_hist[b];
    chunk[t] = s;
    __syncthreads();
    if (t == 0) {
        int cum = 0, tb = 0, A = 0; bool found = false;
        for (int c = 127; c >= 0 && !found; c--) {
            if (cum + chunk[c] >= TOPK) {
                for (int b = c * 32 + 31; b >= c * 32; b--) {
                    if (cum + g_hist[b] >= TOPK) { tb = b; A = cum; found = true; break; }
                    cum += g_hist[b];
                }
            } else cum += chunk[c];
        }
        if (!found) { tb = 0; A = cum - g_hist[0]; }
        g_tbin = tb;
        g_need = TOPK - A;
    }
}

// K3: 4 boxes per thread via float4 score read (better MLP, fewer threads).
__global__ void __launch_bounds__(256) k3_gather() {
    int q = blockIdx.x * 256 + threadIdx.x;        // quad index
    if (q * 4 >= NBOX) return;
    float4 s4 = *(const float4*)(g_score + q * 4);
    int tb = g_tbin;
    float sv[4] = { s4.x, s4.y, s4.z, s4.w };
    #pragma unroll
    for (int u = 0; u < 4; u++) {
        float s = sv[u];
        if (s > CONF_T) {
            unsigned sb = __float_as_uint(s);
            unsigned b  = (sb - BITS04) >> 12;
            if (b >= BINS) b = BINS - 1;
            if ((int)b >= tb) {
                int i = q * 4 + u;
                unsigned long long key = ((unsigned long long)(~sb) << 32) | (unsigned)i;
                if ((int)b > tb) {
                    int c = g_cls[i];
                    int p = atomicAdd(&g_ccount[c], 1);
                    if (p < CAPC) g_ckey[c * CAPC + p] = key;
                } else {
                    int p = atomicAdd(&g_bcnt, 1);
                    if (p < BCAP) g_btbl[p] = key;
                }
            }
        }
    }
}

__global__ void __launch_bounds__(256) k5_nms(const float* __restrict__ pred) {
    __shared__ unsigned long long skey[CAPC];
    __shared__ unsigned long long sbt[BCAP];
    __shared__ float sx1[CAPC], sy1[CAPC], sx2[CAPC], sy2[CAPC], sar[CAPC];
    __shared__ unsigned char skeep[CAPC];
    __shared__ int s_extra;

    const unsigned full = 0xffffffffu;
    int t = threadIdx.x, lane = t & 31;
    int myc = blockIdx.x;
    int cnt = min(g_ccount[myc], CAPC);
    int m = min(g_bcnt, BCAP);
    int need = g_need;

    if (t == 0) s_extra = 0;
    for (int i = t; i < m; i += 256) sbt[i] = g_btbl[i];
    __syncthreads();

    // exact rank inside the boundary bin: top-`need` join the candidate set
    for (int e = t; e < m; e += 256) {
        unsigned long long k = sbt[e];
        int r = 0;
        for (int j = 0; j < m; j++) r += (sbt[j] < k);
        if (r < need) {
            unsigned idx = (unsigned)k;
            if (g_cls[idx] == (unsigned char)myc) {
                int p = atomicAdd(&s_extra, 1);
                if (cnt + p < CAPC) skey[cnt + p] = k;
            }
        }
    }
    for (int i = t; i < cnt; i += 256) skey[i] = g_ckey[myc * CAPC + i];
    __syncthreads();

    int tot = cnt + s_extra;
    if (tot > CAPC) tot = CAPC;
    for (int i = t; i < CAPC; i += 256) if (i >= tot) skey[i] = PADKEY;
    __syncthreads();

    // bitonic sort CAPC keys ascending (= score desc, idx asc)
    for (int k = 2; k <= CAPC; k <<= 1)
        for (int j = k >> 1; j > 0; j >>= 1) {
            for (int i = t; i < CAPC; i += 256) {
                int l = i ^ j;
                if (l > i) {
                    unsigned long long a = skey[i], b = skey[l];
                    bool up = ((i & k) == 0);
                    if ((a > b) == up) { skey[i] = b; skey[l] = a; }
                }
            }
            __syncthreads();
        }

    float off = __fmul_rn((float)myc, MAXWH);
    for (int i = t; i < tot; i += 256) {
        unsigned idx = (unsigned)skey[i];
        const float* p = pred + (size_t)idx * ROW;
        float x = p[0], y = p[1], w = p[2], h = p[3];
        float hw = __fmul_rn(w, 0.5f), hh = __fmul_rn(h, 0.5f);
        float b0 = __fsub_rn(x, hw), b1 = __fsub_rn(y, hh);
        float b2 = __fadd_rn(x, hw), b3 = __fadd_rn(y, hh);
        float q0 = __fadd_rn(b0, off), q1 = __fadd_rn(b1, off);
        float q2 = __fadd_rn(b2, off), q3 = __fadd_rn(b3, off);
        sx1[i] = q0; sy1[i] = q1; sx2[i] = q2; sy2[i] = q3;
        sar[i] = __fmul_rn(__fsub_rn(q2, q0), __fsub_rn(q3, q1));
        skeep[i] = 1;
    }
    __syncthreads();

    // greedy NMS (warp 0, smem-resident; exact ref fp op order)
    if (t < 32) {
        for (int tt = 0; tt < tot; tt++) {
            if (skeep[tt]) {
                float x1 = sx1[tt], y1 = sy1[tt], x2 = sx2[tt], y2 = sy2[tt], a = sar[tt];
                for (int j = tt + 1 + lane; j < tot; j += 32) {
                    float ltx = fmaxf(sx1[j], x1);
                    float lty = fmaxf(sy1[j], y1);
                    float rbx = fminf(sx2[j], x2);
                    float rby = fminf(sy2[j], y2);
                    float ww  = fmaxf(__fsub_rn(rbx, ltx), 0.0f);
                    float hh  = fmaxf(__fsub_rn(rby, lty), 0.0f);
                    float inter = __fmul_rn(ww, hh);
                    float den = __fadd_rn(__fsub_rn(__fadd_rn(a, sar[j]), inter), 1e-9f);
                    if (__fdiv_rn(inter, den) > IOU_T) skeep[j] = 0;
                }
            }
            __syncwarp(full);
        }
    }
    __syncthreads();

    for (int i = t; i < CAPC; i += 256) {
        bool kp = (i < tot) && skeep[i];
        unsigned msk = __ballot_sync(full, kp);
        int base = 0;
        if (lane == 0 && msk) base = atomicAdd(&g_fcnt, __popc(msk));
        base = __shfl_sync(full, base, 0);
        if (kp) {
            g_fkey[base + __popc(msk & ((1u << lane) - 1u))] = skey[i];
            unsigned sb = ~(unsigned)(skey[i] >> 32);
            unsigned b = (sb - BITS04) >> 12;
            if (b >= BINS) b = BINS - 1;
            atomicAdd(&g_hist2[b], 1);
        }
    }
}

__global__ void __launch_bounds__(1024) k8_final(const float* __restrict__ pred,
                                                 float* __restrict__ out) {
    __shared__ unsigned long long fk[FCAP];
    __shared__ int chunk[128];
    __shared__ int s_T2, s_cnt;
    int t = threadIdx.x, lane = t & 31;

    if (t < 128) {
        int s = 0;
        for (int b = t * 32; b < t * 32 + 32; b++) s += g_hist2[b];
        chunk[t] = s;
    }
    if (t == 0) s_cnt = 0;
    __syncthreads();
    if (t == 0) {
        int cum = 0, T2 = 0; bool found = false;
        for (int c = 127; c >= 0 && !found; c--) {
            if (cum + chunk[c] >= MAXDET) {
                for (int b = c * 32 + 31; b >= c * 32; b--) {
                    if (cum + g_hist2[b] >= MAXDET) { T2 = b; found = true; break; }
                    cum += g_hist2[b];
                }
            } else cum += chunk[c];
        }
        s_T2 = found ? T2 : 0;
    }
    for (int i = t; i < FCAP; i += 1024) fk[i] = PADKEY;
    __syncthreads();

    int K = min(g_fcnt, TOPK + 256);
    int T2 = s_T2;
    int Kr = (K + 31) & ~31;
    for (int i = t; i < Kr; i += 1024) {
        bool take = false;
        unsigned long long key = PADKEY;
        if (i < K) {
            key = g_fkey[i];
            unsigned sb = ~(unsigned)(key >> 32);
            unsigned b = (sb - BITS04) >> 12;
            if (b >= BINS) b = BINS - 1;
            take = ((int)b >= T2);
        }
        unsigned msk = __ballot_sync(0xffffffffu, take);
        int base = 0;
        if (lane == 0 && msk) base = atomicAdd(&s_cnt, __popc(msk));
        base = __shfl_sync(0xffffffffu, base, 0);
        if (take) {
            int p = base + __popc(msk & ((1u << lane) - 1u));
            if (p < FCAP) fk[p] = key;
        }
    }
    __syncthreads();

    for (int k = 2; k <= FCAP; k <<= 1)
        for (int j = k >> 1; j > 0; j >>= 1) {
            for (int i = t; i < FCAP; i += 1024) {
                int l = i ^ j;
                if (l > i) {
                    unsigned long long a = fk[i], b = fk[l];
                    bool up = ((i & k) == 0);
                    if ((a > b) == up) { fk[i] = b; fk[l] = a; }
                }
            }
            __syncthreads();
        }

    int m2 = min(s_cnt, FCAP);
    for (int r = t; r < MAXDET; r += 1024) {
        if (r < m2) {
            unsigned long long key = fk[r];
            unsigned idx = (unsigned)key;
            float s = __uint_as_float(~(unsigned)(key >> 32));
            const float* p = pred + (size_t)idx * ROW;
            float x = p[0], y = p[1], w = p[2], h = p[3];
            float hw = __fmul_rn(w, 0.5f), hh = __fmul_rn(h, 0.5f);
            out[r * 6 + 0] = __fsub_rn(x, hw);
            out[r * 6 + 1] = __fsub_rn(y, hh);
            out[r * 6 + 2] = __fadd_rn(x, hw);
            out[r * 6 + 3] = __fadd_rn(y, hh);
            out[r * 6 + 4] = s;
            out[r * 6 + 5] = (float)g_cls[idx];
        }
    }
}

extern "C" void kernel_launch(void* const* d_in, const int* in_sizes, int n_in,
                              void* d_out, int out_size) {
    (void)in_sizes; (void)n_in; (void)out_size;
    const float* pred = (const float*)d_in[0];
    float* out = (float*)d_out;

    static int configured = 0;
    if (!configured) {
        cudaFuncSetAttribute(k1_score, cudaFuncAttributeMaxDynamicSharedMemorySize,
                             RPB * ROW * (int)sizeof(float));
        configured = 1;
    }

    k0_init<<<40, 256>>>(out);
    k1_score<<<(NBOX + RPB - 1) / RPB, RPB, RPB * ROW * (int)sizeof(float)>>>(pred);
    k2_thresh<<<1, 128>>>();
    k3_gather<<<(NBOX / 4 + 255) / 256, 256>>>();
    k5_nms<<<NC, 256>>>(pred);
    k8_final<<<1, 1024>>>(pred, out);
}